// round 2
// baseline (speedup 1.0000x reference)
#include <cuda_runtime.h>

#define TT 512
#define BB_ 64
#define HH 512
#define II 256
#define NG 2048  // 4*H

#define NCTA_REC 128
#define REC_SMEM ((32768 + 8192 + 1024) * 4)

// 256 MB scratch for the precomputed input projection (sanctioned __device__ scratch).
__device__ float g_xg[(size_t)TT * BB_ * NG];
__device__ unsigned g_arrive;

static __device__ __forceinline__ unsigned ld_acq_gpu(unsigned* p) {
  unsigned v;
  asm volatile("ld.acquire.gpu.u32 %0, [%1];" : "=r"(v) : "l"(p) : "memory");
  return v;
}

static __device__ __forceinline__ float fast_sigmoid(float x) {
  return __fdividef(1.0f, 1.0f + __expf(-x));
}
static __device__ __forceinline__ float fast_tanh(float x) {
  float ax = fabsf(x);
  float e = __expf(-2.0f * ax);
  float r = __fdividef(1.0f - e, 1.0f + e);
  return copysignf(r, x);
}

// ---------------------------------------------------------------------------
// Phase 1: xg[t*B+b, n] = sum_k x[t,b,k] * w_ih[n,k] + b_ih[n] + b_hh[n]
// Classic 128x128x16 SGEMM tile, 256 threads, 8x8 per-thread micro-tile.
// Also resets the grid-barrier counter so graph replays are deterministic.
// ---------------------------------------------------------------------------
__global__ __launch_bounds__(256) void xg_gemm_kernel(
    const float* __restrict__ x, const float* __restrict__ w_ih,
    const float* __restrict__ b_ih, const float* __restrict__ b_hh) {
  if (blockIdx.x == 0 && blockIdx.y == 0 && threadIdx.x == 0) g_arrive = 0u;

  __shared__ float Asm[16][132];
  __shared__ float Bsm[16][132];

  const int tid = threadIdx.x;
  const int tx = tid & 15;
  const int ty = tid >> 4;
  const int m0 = blockIdx.y * 128;
  const int n0 = blockIdx.x * 128;

  float acc[8][8];
#pragma unroll
  for (int i = 0; i < 8; ++i)
#pragma unroll
    for (int j = 0; j < 8; ++j) acc[i][j] = 0.0f;

  for (int k0 = 0; k0 < II; k0 += 16) {
#pragma unroll
    for (int r = 0; r < 2; ++r) {
      int idx = tid + r * 256;      // 0..511
      int m = idx >> 2;             // 0..127
      int kq = idx & 3;             // float4 within 16-wide k slab
      float4 v = *reinterpret_cast<const float4*>(
          &x[(size_t)(m0 + m) * II + k0 + kq * 4]);
      Asm[kq * 4 + 0][m] = v.x; Asm[kq * 4 + 1][m] = v.y;
      Asm[kq * 4 + 2][m] = v.z; Asm[kq * 4 + 3][m] = v.w;
      float4 w = *reinterpret_cast<const float4*>(
          &w_ih[(size_t)(n0 + m) * II + k0 + kq * 4]);
      Bsm[kq * 4 + 0][m] = w.x; Bsm[kq * 4 + 1][m] = w.y;
      Bsm[kq * 4 + 2][m] = w.z; Bsm[kq * 4 + 3][m] = w.w;
    }
    __syncthreads();
#pragma unroll
    for (int kk = 0; kk < 16; ++kk) {
      float4 a0 = *reinterpret_cast<const float4*>(&Asm[kk][ty * 4]);
      float4 a1 = *reinterpret_cast<const float4*>(&Asm[kk][64 + ty * 4]);
      float4 q0 = *reinterpret_cast<const float4*>(&Bsm[kk][tx * 4]);
      float4 q1 = *reinterpret_cast<const float4*>(&Bsm[kk][64 + tx * 4]);
      float av[8] = {a0.x, a0.y, a0.z, a0.w, a1.x, a1.y, a1.z, a1.w};
      float bv[8] = {q0.x, q0.y, q0.z, q0.w, q1.x, q1.y, q1.z, q1.w};
#pragma unroll
      for (int i = 0; i < 8; ++i)
#pragma unroll
        for (int j = 0; j < 8; ++j) acc[i][j] = fmaf(av[i], bv[j], acc[i][j]);
    }
    __syncthreads();
  }

  const float4* bi4 = reinterpret_cast<const float4*>(b_ih);
  const float4* bh4 = reinterpret_cast<const float4*>(b_hh);
  int nb = (n0 >> 2) + tx;
  float4 u0 = bi4[nb], v0 = bh4[nb];
  float4 u1 = bi4[nb + 16], v1 = bh4[nb + 16];
  float4 bias0 = make_float4(u0.x + v0.x, u0.y + v0.y, u0.z + v0.z, u0.w + v0.w);
  float4 bias1 = make_float4(u1.x + v1.x, u1.y + v1.y, u1.z + v1.z, u1.w + v1.w);

#pragma unroll
  for (int hm = 0; hm < 2; ++hm)
#pragma unroll
    for (int i = 0; i < 4; ++i) {
      int m = m0 + hm * 64 + ty * 4 + i;
      int mi = hm * 4 + i;
      float* dst = &g_xg[(size_t)m * NG + n0];
      float4 o0 = make_float4(acc[mi][0] + bias0.x, acc[mi][1] + bias0.y,
                              acc[mi][2] + bias0.z, acc[mi][3] + bias0.w);
      float4 o1 = make_float4(acc[mi][4] + bias1.x, acc[mi][5] + bias1.y,
                              acc[mi][6] + bias1.z, acc[mi][7] + bias1.w);
      *reinterpret_cast<float4*>(&dst[tx * 4]) = o0;
      *reinterpret_cast<float4*>(&dst[64 + tx * 4]) = o1;
    }
}

// ---------------------------------------------------------------------------
// Phase 2: persistent recurrent kernel. 128 CTAs (all resident), 256 threads.
// CTA = (j-block of 16) x (b-block of 16). w_hh slice (16j x 4g x 512k,
// 128 KB) loaded to smem ONCE. Each step: load h tile (16x512) to smem,
// 32-acc register-tiled dot with k split 8 ways, shuffle-reduce, gate math
// (one output per thread, c in a register), write h into d_out[t] which the
// next step reads back. Grid barrier = monotonic atomic counter.
// ---------------------------------------------------------------------------
__global__ __launch_bounds__(256, 1) void lstm_rec_kernel(
    const float* __restrict__ h0, const float* __restrict__ c0,
    const float* __restrict__ w_hh, float* __restrict__ out) {
  extern __shared__ float sm[];
  float* Wsm = sm;                   // 16*4*512 = 32768 floats
  float* hsm = sm + 32768;           // 16*512  = 8192 floats
  float* gsm = sm + 32768 + 8192;    // 256*4   = 1024 floats

  const int tid = threadIdx.x;
  const int jblk = blockIdx.x & 31;  // 32 j-blocks
  const int bblk = blockIdx.x >> 5;  // 4 b-blocks
  const int j0 = jblk * 16;
  const int b0 = bblk * 16;

  // --- load w_hh slice into smem: Wsm[(jl*4+g)*512 + k] ---
  {
    const float4* w4 = reinterpret_cast<const float4*>(w_hh);
    float4* Wd = reinterpret_cast<float4*>(Wsm);
#pragma unroll
    for (int r = 0; r < 32; ++r) {
      int f4 = tid + r * 256;        // 0..8191
      int row = f4 >> 7;             // jl*4+g, 0..63
      int col = f4 & 127;
      int jl = row >> 2, g = row & 3;
      Wd[f4] = w4[(size_t)(g * HH + j0 + jl) * (HH / 4) + col];
    }
  }

  // dot-phase role: tid = tile*8 + ks ; tile = bt*8 + jt
  const int ks = tid & 7;            // k-split lane (8-way)
  const int tile = tid >> 3;
  const int jt = tile & 7;           // 8 j-tiles of 2
  const int bt = tile >> 3;          // 4 b-tiles of 4

  // activation-phase role: one (b,j) output per thread
  const int jl_o = tid & 15;
  const int bl_o = tid >> 4;
  const int b_o = b0 + bl_o;
  const int j_o = j0 + jl_o;

  float creg = c0[(size_t)b_o * HH + j_o];

  float* hf = out + (size_t)TT * BB_ * HH;
  float* cf = hf + (size_t)BB_ * HH;

  for (int t = 0; t < TT; ++t) {
    // load this CTA's 16 h rows (contiguous) into smem
    const float* hsrc = (t == 0)
        ? (h0 + (size_t)b0 * HH)
        : (out + (size_t)(t - 1) * BB_ * HH + (size_t)b0 * HH);
    const float4* hs4 = reinterpret_cast<const float4*>(hsrc);
    float4* hd4 = reinterpret_cast<float4*>(hsm);
#pragma unroll
    for (int r = 0; r < 8; ++r) hd4[tid + r * 256] = hs4[tid + r * 256];

    // prefetch this thread's xg gates (hides DRAM latency behind the dot)
    const float* xrow = g_xg + ((size_t)t * BB_ + b_o) * NG + j_o;
    float xg0 = xrow[0];
    float xg1 = xrow[HH];
    float xg2 = xrow[2 * HH];
    float xg3 = xrow[3 * HH];

    __syncthreads();

    float acc[4][2][4];
#pragma unroll
    for (int i = 0; i < 4; ++i)
#pragma unroll
      for (int jj = 0; jj < 2; ++jj)
#pragma unroll
        for (int g = 0; g < 4; ++g) acc[i][jj][g] = 0.0f;

#pragma unroll 4
    for (int m = 0; m < 16; ++m) {
      const int kb = m * 32 + ks * 4;  // interleaved k-chunks: conflict-free
      float4 hv[4];
#pragma unroll
      for (int i = 0; i < 4; ++i)
        hv[i] = *reinterpret_cast<const float4*>(&hsm[(bt * 4 + i) * HH + kb]);
#pragma unroll
      for (int jj = 0; jj < 2; ++jj)
#pragma unroll
        for (int g = 0; g < 4; ++g) {
          float4 wv = *reinterpret_cast<const float4*>(
              &Wsm[((jt * 2 + jj) * 4 + g) * HH + kb]);
#pragma unroll
          for (int i = 0; i < 4; ++i) {
            float s = acc[i][jj][g];
            s = fmaf(hv[i].x, wv.x, s);
            s = fmaf(hv[i].y, wv.y, s);
            s = fmaf(hv[i].z, wv.z, s);
            s = fmaf(hv[i].w, wv.w, s);
            acc[i][jj][g] = s;
          }
        }
    }

    // reduce the 8 k-split lanes, stage gates to smem
#pragma unroll
    for (int i = 0; i < 4; ++i)
#pragma unroll
      for (int jj = 0; jj < 2; ++jj) {
#pragma unroll
        for (int g = 0; g < 4; ++g) {
          float v = acc[i][jj][g];
          v += __shfl_xor_sync(0xffffffffu, v, 1);
          v += __shfl_xor_sync(0xffffffffu, v, 2);
          v += __shfl_xor_sync(0xffffffffu, v, 4);
          acc[i][jj][g] = v;
        }
        if (ks == 0) {
          int o = (bt * 4 + i) * 16 + jt * 2 + jj;
          *reinterpret_cast<float4*>(&gsm[o * 4]) =
              make_float4(acc[i][jj][0], acc[i][jj][1],
                          acc[i][jj][2], acc[i][jj][3]);
        }
      }
    __syncthreads();

    // gate math: one output per thread, c stays in a register
    float4 gv = *reinterpret_cast<const float4*>(&gsm[tid * 4]);
    float ig = fast_sigmoid(gv.x + xg0);
    float fg = fast_sigmoid(gv.y + xg1);
    float tg = fast_tanh(gv.z + xg2);
    float og = fast_sigmoid(gv.w + xg3);
    float c = fg * creg + ig * tg;
    creg = c;
    float h = og * fast_tanh(c);

    out[(size_t)t * BB_ * HH + (size_t)b_o * HH + j_o] = h;
    if (t == TT - 1) {
      hf[(size_t)b_o * HH + j_o] = h;
      cf[(size_t)b_o * HH + j_o] = c;
    }

    // grid barrier (all 128 CTAs resident; monotonic counter, reset by gemm)
    if (t != TT - 1) {
      __threadfence();
      __syncthreads();
      if (tid == 0) {
        atomicAdd(&g_arrive, 1u);
        const unsigned target = (unsigned)(t + 1) * (unsigned)NCTA_REC;
        while (ld_acq_gpu(&g_arrive) < target) {
        }
      }
      __syncthreads();
    }
  }
}

extern "C" void kernel_launch(void* const* d_in, const int* in_sizes, int n_in,
                              void* d_out, int out_size) {
  (void)in_sizes; (void)n_in; (void)out_size;
  const float* x    = (const float*)d_in[0];
  const float* h0   = (const float*)d_in[1];
  const float* c0   = (const float*)d_in[2];
  const float* w_ih = (const float*)d_in[3];
  const float* w_hh = (const float*)d_in[4];
  const float* b_ih = (const float*)d_in[5];
  const float* b_hh = (const float*)d_in[6];
  float* out = (float*)d_out;

  cudaFuncSetAttribute(lstm_rec_kernel,
                       cudaFuncAttributeMaxDynamicSharedMemorySize, REC_SMEM);

  // Phase 1: input projection for all timesteps (also resets barrier state)
  xg_gemm_kernel<<<dim3(NG / 128, (TT * BB_) / 128), 256>>>(x, w_ih, b_ih, b_hh);
  // Phase 2: persistent recurrence
  lstm_rec_kernel<<<NCTA_REC, 256, REC_SMEM>>>(h0, c0, w_hh, out);
}